// round 7
// baseline (speedup 1.0000x reference)
#include <cuda_runtime.h>
#include <cuda_bf16.h>
#include <stdint.h>
#include <math.h>

#define BATCH 4096
#define NNOTES 48
#define NU 256
#define NG 1024
#define MTOT (BATCH * NNOTES)

// ==================== device scratch ====================
__device__ float g_xg0[(size_t)NNOTES * BATCH * NG];
__device__ float g_h1all[(size_t)NNOTES * BATCH * NU];
__device__ float g_c0[BATCH * NU];
__device__ float g_c1[BATCH * NU];
__device__ __align__(128) __nv_bfloat16 g_h0h[2][BATCH * NU];
__device__ __align__(128) __nv_bfloat16 g_h0l[2][BATCH * NU];
__device__ __align__(128) __nv_bfloat16 g_h1h[2][BATCH * NU];
__device__ __align__(128) __nv_bfloat16 g_h1l[2][BATCH * NU];
__device__ __align__(128) __nv_bfloat16 g_xh[(size_t)MTOT * 256];
__device__ __align__(128) __nv_bfloat16 g_xl[(size_t)MTOT * 256];
__device__ __align__(128) __nv_bfloat16 g_w0h[NG * 256], g_w0l[NG * 256];
__device__ __align__(128) __nv_bfloat16 g_whh0h[NG * 256], g_whh0l[NG * 256];
__device__ __align__(128) __nv_bfloat16 g_wcath[NG * 512], g_wcatl[NG * 512];
__device__ float g_w0ext[NG * 4];
__device__ float g_bias0[NG];
__device__ float g_bias1[NG];

__device__ __forceinline__ float sigf(float x) { return 1.0f / (1.0f + expf(-x)); }

__device__ __forceinline__ int permR(int c) {
    int W = c >> 6, cc = c & 63;
    int f = cc >> 3, r = cc & 7;
    int tig = r >> 1, e = r & 1;
    int v = (f & 3) * 4 + tig;
    int gate = (f >> 2) * 2 + e;
    int u = W * 16 + v;
    return gate * 256 + u;
}

__device__ __forceinline__ void split_bf16(float x, __nv_bfloat16& hi, __nv_bfloat16& lo) {
    hi = __float2bfloat16_rn(x);
    lo = __float2bfloat16_rn(x - __bfloat162float(hi));
}
union BF8 { __nv_bfloat16 b[8]; uint4 u; };

// ==================== prep kernels ====================
__global__ void prep_w(const float* __restrict__ W_ih0,
                       const float* __restrict__ W_hh0,
                       const float* __restrict__ W_ih1,
                       const float* __restrict__ W_hh1,
                       const float* __restrict__ b_ih0,
                       const float* __restrict__ b_hh0,
                       const float* __restrict__ b_ih1,
                       const float* __restrict__ b_hh1) {
    int tid = blockIdx.x * blockDim.x + threadIdx.x;
    int stride = gridDim.x * blockDim.x;
    for (int i = tid; i < NG * 256; i += stride) {
        int c = i >> 8, k = i & 255, R = permR(c);
        split_bf16(W_ih0[R * 259 + k], g_w0h[i], g_w0l[i]);
        split_bf16(W_hh0[R * 256 + k], g_whh0h[i], g_whh0l[i]);
    }
    for (int i = tid; i < NG * 512; i += stride) {
        int c = i >> 9, k = i & 511, R = permR(c);
        float x = (k < 256) ? W_ih1[R * 256 + k] : W_hh1[R * 256 + (k - 256)];
        split_bf16(x, g_wcath[i], g_wcatl[i]);
    }
    for (int i = tid; i < NG * 4; i += stride) {
        int c = i >> 2, t = i & 3, R = permR(c);
        g_w0ext[i] = (t < 3) ? W_ih0[R * 259 + 256 + t] : 0.0f;
    }
    for (int i = tid; i < NG; i += stride) {
        int R = permR(i);
        g_bias0[i] = b_ih0[R] + b_hh0[R];
        g_bias1[i] = b_ih1[R] + b_hh1[R];
    }
    __nv_bfloat16 z = __float2bfloat16(0.0f);
    for (int i = tid; i < BATCH * NU; i += stride) {
        g_c0[i] = 0.0f; g_c1[i] = 0.0f;
        g_h0h[0][i] = z; g_h0l[0][i] = z;
        g_h1h[0][i] = z; g_h1l[0][i] = z;
    }
}

__global__ void prep_x(const float* __restrict__ nf) {
    size_t idx = (size_t)blockIdx.x * blockDim.x + threadIdx.x;
    if (idx >= (size_t)MTOT * 32) return;
    int k8 = (int)(idx & 31) * 8;
    int m = (int)(idx >> 5);
    int b = m & 4095, nn = m >> 12;
    const float* src = nf + (((size_t)b * NNOTES + nn) << 8) + k8;
    float4 a = *(const float4*)src, c4 = *(const float4*)(src + 4);
    float v[8] = {a.x, a.y, a.z, a.w, c4.x, c4.y, c4.z, c4.w};
    BF8 hh, ll;
#pragma unroll
    for (int i = 0; i < 8; i++) split_bf16(v[i], hh.b[i], ll.b[i]);
    *(uint4*)&g_xh[(size_t)m * 256 + k8] = hh.u;
    *(uint4*)&g_xl[(size_t)m * 256 + k8] = ll.u;
}

// ==================== mma / cp.async helpers ====================
__device__ __forceinline__ uint32_t smem_u32(const void* p) {
    uint32_t a;
    asm("{ .reg .u64 t; cvta.to.shared.u64 t, %1; cvt.u32.u64 %0, t; }" : "=r"(a) : "l"(p));
    return a;
}
__device__ __forceinline__ void cpa16(uint32_t dst, const void* src) {
    asm volatile("cp.async.cg.shared.global [%0], [%1], 16;" :: "r"(dst), "l"(src) : "memory");
}
__device__ __forceinline__ void ldsm_x4(uint32_t addr, uint32_t& r0, uint32_t& r1,
                                        uint32_t& r2, uint32_t& r3) {
    asm volatile("ldmatrix.sync.aligned.m8n8.x4.shared.b16 {%0,%1,%2,%3}, [%4];"
                 : "=r"(r0), "=r"(r1), "=r"(r2), "=r"(r3) : "r"(addr));
}
__device__ __forceinline__ void mma_bf16(float* d, const uint32_t* a, const uint32_t* b) {
    asm volatile(
        "mma.sync.aligned.m16n8k16.row.col.f32.bf16.bf16.f32 "
        "{%0,%1,%2,%3},{%4,%5,%6,%7},{%8,%9},{%0,%1,%2,%3};"
        : "+f"(d[0]), "+f"(d[1]), "+f"(d[2]), "+f"(d[3])
        : "r"(a[0]), "r"(a[1]), "r"(a[2]), "r"(a[3]), "r"(b[0]), "r"(b[1]));
}

// ==================== unified GEMM body + fused LSTM epilogue ====================
// Split-2 via K-concat: C = Ah.Bh + Ah.Bl + Al.Bh as one K'=3K GEMM.
// MODE 0: xg0 = x @ W0^T + bias0 + ext (K'=768)
// MODE 1: gates = h0 @ Whh0^T + xg0[n]; LSTM -> h0,c0 (K'=768)
// MODE 2: gates = [h0|h1] @ Wcat^T + bias1; LSTM -> h1,c1,h1all (K'=1536)
// CTA tile 128x128, BK=64, 3-stage cp.async ring, 2 CTAs/SM.
#define STAGE_BYTES 36864   // A(128*144) + B(128*144)

template <int MODE>
__device__ __forceinline__ void run_gemm(const float* __restrict__ cn, int n, int mt) {
    constexpr int NCH = (MODE == 2) ? 24 : 12;   // K' / 64
    extern __shared__ __align__(128) char dynsmem[];
    const uint32_t smem_base = smem_u32(dynsmem);

    const int t = threadIdx.x;
    const int bm = mt * 128;
    const int bn = blockIdx.x * 128;
    const int lane = t & 31, warp = t >> 5;
    const int wm = warp & 3, wn = warp >> 2;
    const int seg = t & 7, r0 = t >> 3;          // loader: 8 segs x 32 rows
    const int pPrev = n & 1, pNew = (n & 1) ^ 1;

    auto issue = [&](int ck, int s) {
        const char *Asrc, *Bsrc;
        int kkA, kkB;
        size_t bpitch;
        if (MODE == 0) {
            int term = ck >> 2, kk = (ck & 3) * 64;
            Asrc = (const char*)((term < 2) ? g_xh : g_xl);
            Bsrc = (const char*)((term == 1) ? g_w0l : g_w0h);
            kkA = kk; kkB = kk; bpitch = 512;
        } else if (MODE == 1) {
            int term = ck >> 2, kk = (ck & 3) * 64;
            Asrc = (const char*)((term < 2) ? g_h0h[pPrev] : g_h0l[pPrev]);
            Bsrc = (const char*)((term == 1) ? g_whh0l : g_whh0h);
            kkA = kk; kkB = kk; bpitch = 512;
        } else {
            int term = ck >> 3, kk = (ck & 7) * 64;
            bool lo = (term == 2);
            if (kk < 256) {
                Asrc = (const char*)(lo ? g_h0l[pNew] : g_h0h[pNew]);
                kkA = kk;
            } else {
                Asrc = (const char*)(lo ? g_h1l[pPrev] : g_h1h[pPrev]);
                kkA = kk - 256;
            }
            Bsrc = (const char*)((term == 1) ? g_wcatl : g_wcath);
            kkB = kk; bpitch = 1024;
        }
        uint32_t dA = smem_base + s * STAGE_BYTES;
        uint32_t dB = dA + 18432;
#pragma unroll
        for (int h = 0; h < 4; h++) {
            int row = r0 + h * 32;
            cpa16(dA + row * 144 + seg * 16,
                  Asrc + (size_t)(bm + row) * 512 + kkA * 2 + seg * 16);
            cpa16(dB + row * 144 + seg * 16,
                  Bsrc + (size_t)(bn + row) * bpitch + kkB * 2 + seg * 16);
        }
        asm volatile("cp.async.commit_group;" ::: "memory");
    };

    float acc[2][8][4];
#pragma unroll
    for (int mi = 0; mi < 2; mi++)
#pragma unroll
        for (int f = 0; f < 8; f++)
#pragma unroll
            for (int x = 0; x < 4; x++) acc[mi][f][x] = 0.0f;

    issue(0, 0); issue(1, 1);

    for (int ck = 0; ck < NCH; ck++) {
        if (ck == NCH - 1) asm volatile("cp.async.wait_group 0;" ::: "memory");
        else               asm volatile("cp.async.wait_group 1;" ::: "memory");
        __syncthreads();
        if (ck + 2 < NCH) issue(ck + 2, (ck + 2) % 3);

        uint32_t sAb = smem_base + (ck % 3) * STAGE_BYTES;
        uint32_t sBb = sAb + 18432;
#pragma unroll
        for (int ks = 0; ks < 4; ks++) {
            uint32_t A[2][4];
#pragma unroll
            for (int mi = 0; mi < 2; mi++) {
                uint32_t addr = sAb + (wm * 32 + mi * 16 + (lane & 15)) * 144 +
                                ks * 32 + (lane >> 4) * 16;
                ldsm_x4(addr, A[mi][0], A[mi][1], A[mi][2], A[mi][3]);
            }
            uint32_t B[4][4];
#pragma unroll
            for (int fp = 0; fp < 4; fp++) {
                uint32_t addr = sBb + (wn * 64 + fp * 16 + (lane >> 4) * 8 + (lane & 7)) * 144 +
                                ks * 32 + ((lane >> 3) & 1) * 16;
                ldsm_x4(addr, B[fp][0], B[fp][1], B[fp][2], B[fp][3]);
            }
#pragma unroll
            for (int fp = 0; fp < 4; fp++) {
#pragma unroll
                for (int mi = 0; mi < 2; mi++) {
                    mma_bf16(acc[mi][2 * fp + 0], A[mi], &B[fp][0]);
                    mma_bf16(acc[mi][2 * fp + 1], A[mi], &B[fp][2]);
                }
            }
        }
    }

    // ------------- fused epilogue -------------
    if (MODE == 0) {
        int rowm[4];
        float sv[4][3];
#pragma unroll
        for (int rid = 0; rid < 4; rid++) {
            int mi = rid >> 1, rh = rid & 1;
            int m = bm + wm * 32 + mi * 16 + rh * 8 + (lane >> 2);
            rowm[rid] = m;
            int b = m & 4095, nn = m >> 12;
            if (nn > 0) {
                const float* p = cn + ((size_t)b * NNOTES + (nn - 1)) * 3;
                sv[rid][0] = p[0]; sv[rid][1] = p[1]; sv[rid][2] = p[2];
            } else {
                sv[rid][0] = sv[rid][1] = sv[rid][2] = 0.0f;
            }
        }
#pragma unroll
        for (int f = 0; f < 8; f++) {
            int c = bn + wn * 64 + 8 * f + 2 * (lane & 3);
            float2 bia = *(const float2*)&g_bias0[c];
            float4 e0 = *(const float4*)&g_w0ext[(size_t)c * 4];
            float4 e1 = *(const float4*)&g_w0ext[(size_t)(c + 1) * 4];
#pragma unroll
            for (int rid = 0; rid < 4; rid++) {
                int mi = rid >> 1, rh = rid & 1;
                float2 o;
                o.x = acc[mi][f][rh * 2 + 0] + bia.x +
                      sv[rid][0] * e0.x + sv[rid][1] * e0.y + sv[rid][2] * e0.z;
                o.y = acc[mi][f][rh * 2 + 1] + bia.y +
                      sv[rid][0] * e1.x + sv[rid][1] * e1.y + sv[rid][2] * e1.z;
                *(float2*)&g_xg0[(size_t)rowm[rid] * NG + c] = o;
            }
        }
    } else {
#pragma unroll
        for (int rid = 0; rid < 4; rid++) {
            int mi = rid >> 1, rh = rid & 1;
            int m = bm + wm * 32 + mi * 16 + rh * 8 + (lane >> 2);
#pragma unroll
            for (int v = 0; v < 4; v++) {
                int cif = bn + wn * 64 + 8 * v + 2 * (lane & 3);
                float2 aif, ago;
                if (MODE == 1) {
                    const float* xb = g_xg0 + (size_t)n * ((size_t)BATCH * NG) + (size_t)m * NG;
                    aif = *(const float2*)&xb[cif];
                    ago = *(const float2*)&xb[cif + 32];
                } else {
                    aif = *(const float2*)&g_bias1[cif];
                    ago = *(const float2*)&g_bias1[cif + 32];
                }
                float gi = acc[mi][v][rh * 2 + 0] + aif.x;
                float gf = acc[mi][v][rh * 2 + 1] + aif.y;
                float gg = acc[mi][v + 4][rh * 2 + 0] + ago.x;
                float go = acc[mi][v + 4][rh * 2 + 1] + ago.y;
                int u = ((bn + wn * 64) >> 6) * 16 + v * 4 + (lane & 3);
                int idx = m * 256 + u;
                float* cptr = (MODE == 1) ? g_c0 : g_c1;
                float cp = cptr[idx];
                float cnew = sigf(gf) * cp + sigf(gi) * tanhf(gg);
                float h = sigf(go) * tanhf(cnew);
                cptr[idx] = cnew;
                __nv_bfloat16 hh = __float2bfloat16_rn(h);
                __nv_bfloat16 hl = __float2bfloat16_rn(h - __bfloat162float(hh));
                if (MODE == 1) {
                    g_h0h[pNew][idx] = hh; g_h0l[pNew][idx] = hl;
                } else {
                    g_h1h[pNew][idx] = hh; g_h1l[pNew][idx] = hl;
                    g_h1all[(size_t)n * (BATCH * NU) + idx] = h;
                }
            }
        }
    }
}

template <int MODE>
__global__ void __launch_bounds__(256, 2) mma_gemm(const float* __restrict__ cn, int n) {
    run_gemm<MODE>(cn, n, blockIdx.y);
}

// Combined launch: blocks [0,32) do mode2(n); blocks [32,64) do mode1(n+1).
__global__ void __launch_bounds__(256, 2) mma_combined(int n) {
    if (blockIdx.y < 32) run_gemm<2>(nullptr, n, blockIdx.y);
    else                 run_gemm<1>(nullptr, n + 1, blockIdx.y - 32);
}

// ==================== final projection ====================
__global__ void final_out(const float* __restrict__ Wout, const float* __restrict__ bout,
                          float* __restrict__ out) {
    int gwarp = (blockIdx.x * blockDim.x + threadIdx.x) >> 5;
    int lane = threadIdx.x & 31;
    if (gwarp >= MTOT) return;
    int b = gwarp / NNOTES, n = gwarp % NNOTES;
    const float* hrow = &g_h1all[(size_t)n * (BATCH * NU) + (size_t)b * NU];

    float s0 = 0.0f, s1 = 0.0f, s2 = 0.0f;
    int u = lane * 8;
    float4 v0 = *(const float4*)&hrow[u];
    float4 v1 = *(const float4*)&hrow[u + 4];
    float hv[8] = {v0.x, v0.y, v0.z, v0.w, v1.x, v1.y, v1.z, v1.w};
#pragma unroll
    for (int i = 0; i < 8; i++) {
        float h = hv[i];
        s0 += h * Wout[0 * NU + u + i];
        s1 += h * Wout[1 * NU + u + i];
        s2 += h * Wout[2 * NU + u + i];
    }
#pragma unroll
    for (int off = 16; off > 0; off >>= 1) {
        s0 += __shfl_xor_sync(0xffffffffu, s0, off);
        s1 += __shfl_xor_sync(0xffffffffu, s1, off);
        s2 += __shfl_xor_sync(0xffffffffu, s2, off);
    }
    if (lane == 0) {
        float* o = &out[(size_t)b * (NNOTES * 3) + (size_t)n * 3];
        o[0] = sigf(s0 + bout[0]);
        o[1] = sigf(s1 + bout[1]);
        o[2] = s2 + bout[2];
    }
}

// ==================== launch ====================
extern "C" void kernel_launch(void* const* d_in, const int* in_sizes, int n_in,
                              void* d_out, int out_size) {
    const float* nf    = (const float*)d_in[0];
    const float* cn    = (const float*)d_in[1];
    const float* W_ih0 = (const float*)d_in[2];
    const float* W_hh0 = (const float*)d_in[3];
    const float* b_ih0 = (const float*)d_in[4];
    const float* b_hh0 = (const float*)d_in[5];
    const float* W_ih1 = (const float*)d_in[6];
    const float* W_hh1 = (const float*)d_in[7];
    const float* b_ih1 = (const float*)d_in[8];
    const float* b_hh1 = (const float*)d_in[9];
    const float* W_out = (const float*)d_in[10];
    const float* b_out = (const float*)d_in[11];
    float* out = (float*)d_out;

    const int DYNSMEM = 3 * STAGE_BYTES;  // 110592
    cudaFuncSetAttribute(mma_gemm<0>, cudaFuncAttributeMaxDynamicSharedMemorySize, DYNSMEM);
    cudaFuncSetAttribute(mma_gemm<1>, cudaFuncAttributeMaxDynamicSharedMemorySize, DYNSMEM);
    cudaFuncSetAttribute(mma_gemm<2>, cudaFuncAttributeMaxDynamicSharedMemorySize, DYNSMEM);
    cudaFuncSetAttribute(mma_combined, cudaFuncAttributeMaxDynamicSharedMemorySize, DYNSMEM);

    prep_w<<<1024, 256>>>(W_ih0, W_hh0, W_ih1, W_hh1, b_ih0, b_hh0, b_ih1, b_hh1);
    prep_x<<<(MTOT * 32 + 255) / 256, 256>>>(nf);

    // layer-0 input GEMM over all notes
    mma_gemm<0><<<dim3(NG / 128, MTOT / 128), 256, DYNSMEM>>>(cn, 0);

    // recurrence: mode1(0); then {mode2(n) || mode1(n+1)}; then mode2(47)
    mma_gemm<1><<<dim3(8, 32), 256, DYNSMEM>>>(nullptr, 0);
    for (int n = 0; n < NNOTES - 1; n++)
        mma_combined<<<dim3(8, 64), 256, DYNSMEM>>>(n);
    mma_gemm<2><<<dim3(8, 32), 256, DYNSMEM>>>(nullptr, NNOTES - 1);

    int blocks = (MTOT * 32 + 255) / 256;
    final_out<<<blocks, 256>>>(W_out, b_out, out);
}

// round 8
// speedup vs baseline: 1.0718x; 1.0718x over previous
#include <cuda_runtime.h>
#include <cuda_bf16.h>
#include <stdint.h>
#include <math.h>

#define BATCH 4096
#define NNOTES 48
#define NU 256
#define NG 1024
#define MTOT (BATCH * NNOTES)

// ==================== device scratch ====================
__device__ float g_xg0[(size_t)NNOTES * BATCH * NG];
__device__ float g_h1all[(size_t)NNOTES * BATCH * NU];
__device__ float g_c0[BATCH * NU];
__device__ float g_c1[BATCH * NU];
__device__ __align__(128) __nv_bfloat16 g_h0h[2][BATCH * NU];
__device__ __align__(128) __nv_bfloat16 g_h0l[2][BATCH * NU];
__device__ __align__(128) __nv_bfloat16 g_h1h[2][BATCH * NU];
__device__ __align__(128) __nv_bfloat16 g_h1l[2][BATCH * NU];
__device__ __align__(128) __nv_bfloat16 g_xh[(size_t)MTOT * 256];
__device__ __align__(128) __nv_bfloat16 g_xl[(size_t)MTOT * 256];
__device__ __align__(128) __nv_bfloat16 g_w0h[NG * 256], g_w0l[NG * 256];
__device__ __align__(128) __nv_bfloat16 g_whh0h[NG * 256], g_whh0l[NG * 256];
__device__ __align__(128) __nv_bfloat16 g_wcath[NG * 512], g_wcatl[NG * 512];
__device__ float g_w0ext[NG * 4];
__device__ float g_bias0[NG];
__device__ float g_bias1[NG];

__device__ __forceinline__ float sigf(float x) { return 1.0f / (1.0f + expf(-x)); }

__device__ __forceinline__ int permR(int c) {
    int W = c >> 6, cc = c & 63;
    int f = cc >> 3, r = cc & 7;
    int tig = r >> 1, e = r & 1;
    int v = (f & 3) * 4 + tig;
    int gate = (f >> 2) * 2 + e;
    int u = W * 16 + v;
    return gate * 256 + u;
}

__device__ __forceinline__ void split_bf16(float x, __nv_bfloat16& hi, __nv_bfloat16& lo) {
    hi = __float2bfloat16_rn(x);
    lo = __float2bfloat16_rn(x - __bfloat162float(hi));
}
union BF8 { __nv_bfloat16 b[8]; uint4 u; };

// ==================== prep kernels ====================
__global__ void prep_w(const float* __restrict__ W_ih0,
                       const float* __restrict__ W_hh0,
                       const float* __restrict__ W_ih1,
                       const float* __restrict__ W_hh1,
                       const float* __restrict__ b_ih0,
                       const float* __restrict__ b_hh0,
                       const float* __restrict__ b_ih1,
                       const float* __restrict__ b_hh1) {
    int tid = blockIdx.x * blockDim.x + threadIdx.x;
    int stride = gridDim.x * blockDim.x;
    for (int i = tid; i < NG * 256; i += stride) {
        int c = i >> 8, k = i & 255, R = permR(c);
        split_bf16(W_ih0[R * 259 + k], g_w0h[i], g_w0l[i]);
        split_bf16(W_hh0[R * 256 + k], g_whh0h[i], g_whh0l[i]);
    }
    for (int i = tid; i < NG * 512; i += stride) {
        int c = i >> 9, k = i & 511, R = permR(c);
        float x = (k < 256) ? W_ih1[R * 256 + k] : W_hh1[R * 256 + (k - 256)];
        split_bf16(x, g_wcath[i], g_wcatl[i]);
    }
    for (int i = tid; i < NG * 4; i += stride) {
        int c = i >> 2, t = i & 3, R = permR(c);
        g_w0ext[i] = (t < 3) ? W_ih0[R * 259 + 256 + t] : 0.0f;
    }
    for (int i = tid; i < NG; i += stride) {
        int R = permR(i);
        g_bias0[i] = b_ih0[R] + b_hh0[R];
        g_bias1[i] = b_ih1[R] + b_hh1[R];
    }
    __nv_bfloat16 z = __float2bfloat16(0.0f);
    for (int i = tid; i < BATCH * NU; i += stride) {
        g_c0[i] = 0.0f; g_c1[i] = 0.0f;
        g_h0h[0][i] = z; g_h0l[0][i] = z;
        g_h1h[0][i] = z; g_h1l[0][i] = z;
    }
}

__global__ void prep_x(const float* __restrict__ nf) {
    size_t idx = (size_t)blockIdx.x * blockDim.x + threadIdx.x;
    if (idx >= (size_t)MTOT * 32) return;
    int k8 = (int)(idx & 31) * 8;
    int m = (int)(idx >> 5);
    int b = m & 4095, nn = m >> 12;
    const float* src = nf + (((size_t)b * NNOTES + nn) << 8) + k8;
    float4 a = *(const float4*)src, c4 = *(const float4*)(src + 4);
    float v[8] = {a.x, a.y, a.z, a.w, c4.x, c4.y, c4.z, c4.w};
    BF8 hh, ll;
#pragma unroll
    for (int i = 0; i < 8; i++) split_bf16(v[i], hh.b[i], ll.b[i]);
    *(uint4*)&g_xh[(size_t)m * 256 + k8] = hh.u;
    *(uint4*)&g_xl[(size_t)m * 256 + k8] = ll.u;
}

// ==================== mma / cp.async helpers ====================
__device__ __forceinline__ uint32_t smem_u32(const void* p) {
    uint32_t a;
    asm("{ .reg .u64 t; cvta.to.shared.u64 t, %1; cvt.u32.u64 %0, t; }" : "=r"(a) : "l"(p));
    return a;
}
__device__ __forceinline__ void cpa16(uint32_t dst, const void* src) {
    asm volatile("cp.async.cg.shared.global [%0], [%1], 16;" :: "r"(dst), "l"(src) : "memory");
}
__device__ __forceinline__ void ldsm_x4(uint32_t addr, uint32_t& r0, uint32_t& r1,
                                        uint32_t& r2, uint32_t& r3) {
    asm volatile("ldmatrix.sync.aligned.m8n8.x4.shared.b16 {%0,%1,%2,%3}, [%4];"
                 : "=r"(r0), "=r"(r1), "=r"(r2), "=r"(r3) : "r"(addr));
}
__device__ __forceinline__ void mma_bf16(float* d, const uint32_t* a, const uint32_t* b) {
    asm volatile(
        "mma.sync.aligned.m16n8k16.row.col.f32.bf16.bf16.f32 "
        "{%0,%1,%2,%3},{%4,%5,%6,%7},{%8,%9},{%0,%1,%2,%3};"
        : "+f"(d[0]), "+f"(d[1]), "+f"(d[2]), "+f"(d[3])
        : "r"(a[0]), "r"(a[1]), "r"(a[2]), "r"(a[3]), "r"(b[0]), "r"(b[1]));
}

// ==================== unified GEMM body + fused LSTM epilogue ====================
// Split-2 via K-concat: C = Ah.Bh + Ah.Bl + Al.Bh as one K'=3K GEMM.
// MODE 0: xg0 = x @ W0^T + bias0 + ext (K'=768)
// MODE 1: gates = h0 @ Whh0^T + xg0[n]; LSTM -> h0,c0 (K'=768)
// MODE 2: gates = [h0|h1] @ Wcat^T + bias1; LSTM -> h1,c1,h1all (K'=1536)
// CTA tile 128x64, 4 warps (each 32x64), BK=32, 3-stage cp.async ring, 4 CTAs/SM.
#define STAGE_BYTES 15360   // A(128*80) + B(64*80)

template <int MODE>
__device__ __forceinline__ void run_gemm(const float* __restrict__ cn, int n, int mt) {
    constexpr int NCH = (MODE == 2) ? 48 : 24;   // K' / 32
    extern __shared__ __align__(128) char dynsmem[];
    const uint32_t smem_base = smem_u32(dynsmem);

    const int t = threadIdx.x;
    const int bm = mt * 128;
    const int bn = blockIdx.x * 64;
    const int lane = t & 31;
    const int wm = t >> 5;               // 4 warps, all M-strips
    const int seg = t & 3, r0 = t >> 2;  // loader: 4 segs x 32 rows
    const int pPrev = n & 1, pNew = (n & 1) ^ 1;

    auto issue = [&](int ck, int s) {
        const char *Asrc, *Bsrc;
        int kkA, kkB;
        size_t bpitch;
        if (MODE == 0) {
            int term = ck >> 3, kk = (ck & 7) * 32;
            Asrc = (const char*)((term < 2) ? g_xh : g_xl);
            Bsrc = (const char*)((term == 1) ? g_w0l : g_w0h);
            kkA = kk; kkB = kk; bpitch = 512;
        } else if (MODE == 1) {
            int term = ck >> 3, kk = (ck & 7) * 32;
            Asrc = (const char*)((term < 2) ? g_h0h[pPrev] : g_h0l[pPrev]);
            Bsrc = (const char*)((term == 1) ? g_whh0l : g_whh0h);
            kkA = kk; kkB = kk; bpitch = 512;
        } else {
            int term = ck >> 4, kk = (ck & 15) * 32;
            bool lo = (term == 2);
            if (kk < 256) {
                Asrc = (const char*)(lo ? g_h0l[pNew] : g_h0h[pNew]);
                kkA = kk;
            } else {
                Asrc = (const char*)(lo ? g_h1l[pPrev] : g_h1h[pPrev]);
                kkA = kk - 256;
            }
            Bsrc = (const char*)((term == 1) ? g_wcatl : g_wcath);
            kkB = kk; bpitch = 1024;
        }
        uint32_t dA = smem_base + s * STAGE_BYTES;
        uint32_t dB = dA + 10240;
#pragma unroll
        for (int h = 0; h < 4; h++) {
            int row = r0 + h * 32;
            cpa16(dA + row * 80 + seg * 16,
                  Asrc + (size_t)(bm + row) * 512 + kkA * 2 + seg * 16);
        }
#pragma unroll
        for (int h = 0; h < 2; h++) {
            int row = r0 + h * 32;
            cpa16(dB + row * 80 + seg * 16,
                  Bsrc + (size_t)(bn + row) * bpitch + kkB * 2 + seg * 16);
        }
        asm volatile("cp.async.commit_group;" ::: "memory");
    };

    float acc[2][8][4];
#pragma unroll
    for (int mi = 0; mi < 2; mi++)
#pragma unroll
        for (int f = 0; f < 8; f++)
#pragma unroll
            for (int x = 0; x < 4; x++) acc[mi][f][x] = 0.0f;

    issue(0, 0); issue(1, 1);

    for (int ck = 0; ck < NCH; ck++) {
        if (ck == NCH - 1) asm volatile("cp.async.wait_group 0;" ::: "memory");
        else               asm volatile("cp.async.wait_group 1;" ::: "memory");
        __syncthreads();
        if (ck + 2 < NCH) issue(ck + 2, (ck + 2) % 3);

        uint32_t sAb = smem_base + (ck % 3) * STAGE_BYTES;
        uint32_t sBb = sAb + 10240;
#pragma unroll
        for (int ks = 0; ks < 2; ks++) {
            uint32_t A[2][4];
#pragma unroll
            for (int mi = 0; mi < 2; mi++) {
                uint32_t addr = sAb + (wm * 32 + mi * 16 + (lane & 15)) * 80 +
                                ks * 32 + (lane >> 4) * 16;
                ldsm_x4(addr, A[mi][0], A[mi][1], A[mi][2], A[mi][3]);
            }
            uint32_t B[4][4];
#pragma unroll
            for (int fp = 0; fp < 4; fp++) {
                uint32_t addr = sBb + (fp * 16 + (lane >> 4) * 8 + (lane & 7)) * 80 +
                                ks * 32 + ((lane >> 3) & 1) * 16;
                ldsm_x4(addr, B[fp][0], B[fp][1], B[fp][2], B[fp][3]);
            }
#pragma unroll
            for (int fp = 0; fp < 4; fp++) {
#pragma unroll
                for (int mi = 0; mi < 2; mi++) {
                    mma_bf16(acc[mi][2 * fp + 0], A[mi], &B[fp][0]);
                    mma_bf16(acc[mi][2 * fp + 1], A[mi], &B[fp][2]);
                }
            }
        }
    }

    // ------------- fused epilogue -------------
    if (MODE == 0) {
        int rowm[4];
        float sv[4][3];
#pragma unroll
        for (int rid = 0; rid < 4; rid++) {
            int mi = rid >> 1, rh = rid & 1;
            int m = bm + wm * 32 + mi * 16 + rh * 8 + (lane >> 2);
            rowm[rid] = m;
            int b = m & 4095, nn = m >> 12;
            if (nn > 0) {
                const float* p = cn + ((size_t)b * NNOTES + (nn - 1)) * 3;
                sv[rid][0] = p[0]; sv[rid][1] = p[1]; sv[rid][2] = p[2];
            } else {
                sv[rid][0] = sv[rid][1] = sv[rid][2] = 0.0f;
            }
        }
#pragma unroll
        for (int f = 0; f < 8; f++) {
            int c = bn + 8 * f + 2 * (lane & 3);
            float2 bia = *(const float2*)&g_bias0[c];
            float4 e0 = *(const float4*)&g_w0ext[(size_t)c * 4];
            float4 e1 = *(const float4*)&g_w0ext[(size_t)(c + 1) * 4];
#pragma unroll
            for (int rid = 0; rid < 4; rid++) {
                int mi = rid >> 1, rh = rid & 1;
                float2 o;
                o.x = acc[mi][f][rh * 2 + 0] + bia.x +
                      sv[rid][0] * e0.x + sv[rid][1] * e0.y + sv[rid][2] * e0.z;
                o.y = acc[mi][f][rh * 2 + 1] + bia.y +
                      sv[rid][0] * e1.x + sv[rid][1] * e1.y + sv[rid][2] * e1.z;
                *(float2*)&g_xg0[(size_t)rowm[rid] * NG + c] = o;
            }
        }
    } else {
#pragma unroll
        for (int rid = 0; rid < 4; rid++) {
            int mi = rid >> 1, rh = rid & 1;
            int m = bm + wm * 32 + mi * 16 + rh * 8 + (lane >> 2);
#pragma unroll
            for (int v = 0; v < 4; v++) {
                int cif = bn + 8 * v + 2 * (lane & 3);
                float2 aif, ago;
                if (MODE == 1) {
                    const float* xb = g_xg0 + (size_t)n * ((size_t)BATCH * NG) + (size_t)m * NG;
                    aif = *(const float2*)&xb[cif];
                    ago = *(const float2*)&xb[cif + 32];
                } else {
                    aif = *(const float2*)&g_bias1[cif];
                    ago = *(const float2*)&g_bias1[cif + 32];
                }
                float gi = acc[mi][v][rh * 2 + 0] + aif.x;
                float gf = acc[mi][v][rh * 2 + 1] + aif.y;
                float gg = acc[mi][v + 4][rh * 2 + 0] + ago.x;
                float go = acc[mi][v + 4][rh * 2 + 1] + ago.y;
                int u = (bn >> 6) * 16 + v * 4 + (lane & 3);
                int idx = m * 256 + u;
                float* cptr = (MODE == 1) ? g_c0 : g_c1;
                float cp = cptr[idx];
                float cnew = sigf(gf) * cp + sigf(gi) * tanhf(gg);
                float h = sigf(go) * tanhf(cnew);
                cptr[idx] = cnew;
                __nv_bfloat16 hh = __float2bfloat16_rn(h);
                __nv_bfloat16 hl = __float2bfloat16_rn(h - __bfloat162float(hh));
                if (MODE == 1) {
                    g_h0h[pNew][idx] = hh; g_h0l[pNew][idx] = hl;
                } else {
                    g_h1h[pNew][idx] = hh; g_h1l[pNew][idx] = hl;
                    g_h1all[(size_t)n * (BATCH * NU) + idx] = h;
                }
            }
        }
    }
}

template <int MODE>
__global__ void __launch_bounds__(128, 4) mma_gemm(const float* __restrict__ cn, int n) {
    run_gemm<MODE>(cn, n, blockIdx.y);
}

// Combined launch: blocks y in [0,32) do mode2(n); [32,64) do mode1(n+1).
__global__ void __launch_bounds__(128, 4) mma_combined(int n) {
    if (blockIdx.y < 32) run_gemm<2>(nullptr, n, blockIdx.y);
    else                 run_gemm<1>(nullptr, n + 1, blockIdx.y - 32);
}

// ==================== final projection ====================
__global__ void final_out(const float* __restrict__ Wout, const float* __restrict__ bout,
                          float* __restrict__ out) {
    int gwarp = (blockIdx.x * blockDim.x + threadIdx.x) >> 5;
    int lane = threadIdx.x & 31;
    if (gwarp >= MTOT) return;
    int b = gwarp / NNOTES, n = gwarp % NNOTES;
    const float* hrow = &g_h1all[(size_t)n * (BATCH * NU) + (size_t)b * NU];

    float s0 = 0.0f, s1 = 0.0f, s2 = 0.0f;
    int u = lane * 8;
    float4 v0 = *(const float4*)&hrow[u];
    float4 v1 = *(const float4*)&hrow[u + 4];
    float hv[8] = {v0.x, v0.y, v0.z, v0.w, v1.x, v1.y, v1.z, v1.w};
#pragma unroll
    for (int i = 0; i < 8; i++) {
        float h = hv[i];
        s0 += h * Wout[0 * NU + u + i];
        s1 += h * Wout[1 * NU + u + i];
        s2 += h * Wout[2 * NU + u + i];
    }
#pragma unroll
    for (int off = 16; off > 0; off >>= 1) {
        s0 += __shfl_xor_sync(0xffffffffu, s0, off);
        s1 += __shfl_xor_sync(0xffffffffu, s1, off);
        s2 += __shfl_xor_sync(0xffffffffu, s2, off);
    }
    if (lane == 0) {
        float* o = &out[(size_t)b * (NNOTES * 3) + (size_t)n * 3];
        o[0] = sigf(s0 + bout[0]);
        o[1] = sigf(s1 + bout[1]);
        o[2] = s2 + bout[2];
    }
}

// ==================== launch ====================
extern "C" void kernel_launch(void* const* d_in, const int* in_sizes, int n_in,
                              void* d_out, int out_size) {
    const float* nf    = (const float*)d_in[0];
    const float* cn    = (const float*)d_in[1];
    const float* W_ih0 = (const float*)d_in[2];
    const float* W_hh0 = (const float*)d_in[3];
    const float* b_ih0 = (const float*)d_in[4];
    const float* b_hh0 = (const float*)d_in[5];
    const float* W_ih1 = (const float*)d_in[6];
    const float* W_hh1 = (const float*)d_in[7];
    const float* b_ih1 = (const float*)d_in[8];
    const float* b_hh1 = (const float*)d_in[9];
    const float* W_out = (const float*)d_in[10];
    const float* b_out = (const float*)d_in[11];
    float* out = (float*)d_out;

    const int DYNSMEM = 3 * STAGE_BYTES;  // 46080
    cudaFuncSetAttribute(mma_gemm<0>, cudaFuncAttributeMaxDynamicSharedMemorySize, DYNSMEM);
    cudaFuncSetAttribute(mma_gemm<1>, cudaFuncAttributeMaxDynamicSharedMemorySize, DYNSMEM);
    cudaFuncSetAttribute(mma_gemm<2>, cudaFuncAttributeMaxDynamicSharedMemorySize, DYNSMEM);
    cudaFuncSetAttribute(mma_combined, cudaFuncAttributeMaxDynamicSharedMemorySize, DYNSMEM);

    prep_w<<<1024, 256>>>(W_ih0, W_hh0, W_ih1, W_hh1, b_ih0, b_hh0, b_ih1, b_hh1);
    prep_x<<<(MTOT * 32 + 255) / 256, 256>>>(nf);

    // layer-0 input GEMM over all notes
    mma_gemm<0><<<dim3(16, 1536), 128, DYNSMEM>>>(cn, 0);

    // recurrence: mode1(0); then {mode2(n) || mode1(n+1)}; then mode2(47)
    mma_gemm<1><<<dim3(16, 32), 128, DYNSMEM>>>(nullptr, 0);
    for (int n = 0; n < NNOTES - 1; n++)
        mma_combined<<<dim3(16, 64), 128, DYNSMEM>>>(n);
    mma_gemm<2><<<dim3(16, 32), 128, DYNSMEM>>>(nullptr, NNOTES - 1);

    int blocks = (MTOT * 32 + 255) / 256;
    final_out<<<blocks, 256>>>(W_out, b_out, out);
}